// round 3
// baseline (speedup 1.0000x reference)
#include <cuda_runtime.h>
#include <cstdint>

// MessagePassing scatter-add:
//   out[dst[e], :] += x[src[e], :]   for e in [0, E)
// x: [N, 64] f32, edge_index: [2, E] delivered as int32, out: [N, 64] f32.
//
// 16 threads per edge; each thread handles one float4 (16B) chunk of the
// 64-float row. Gather from x (L2-resident, 25.6MB) and accumulate with
// red.global.add.v4.f32 (no-return vector reduction, sm_90+).

static constexpr int D = 64;          // feature dim
static constexpr int CHUNKS = D / 4;  // 16 float4 chunks per row

__global__ void mp_scatter_kernel(const float4* __restrict__ x,
                                  const int* __restrict__ src,
                                  const int* __restrict__ dst,
                                  float* __restrict__ out,
                                  long long total_items) {
    long long gid = (long long)blockIdx.x * blockDim.x + threadIdx.x;
    if (gid >= total_items) return;

    long long e = gid >> 4;        // edge index
    int c = (int)(gid & 15);       // chunk within row

    int s = __ldg(&src[e]);
    int d = __ldg(&dst[e]);

    float4 v = __ldg(&x[(long long)s * CHUNKS + c]);

    float* p = out + (long long)d * D + c * 4;
    asm volatile("red.global.add.v4.f32 [%0], {%1, %2, %3, %4};"
                 :: "l"(p), "f"(v.x), "f"(v.y), "f"(v.z), "f"(v.w)
                 : "memory");
}

extern "C" void kernel_launch(void* const* d_in, const int* in_sizes, int n_in,
                              void* d_out, int out_size) {
    const float4* x = (const float4*)d_in[0];        // [N, 64] f32 as float4[N*16]
    const int* ei = (const int*)d_in[1];             // [2, E] int32 (int64 narrowed by harness)
    float* out = (float*)d_out;                      // [N, 64] f32

    long long E = (long long)in_sizes[1] / 2;
    const int* src = ei;
    const int* dst = ei + E;

    // d_out is poisoned; reference leaves isolated nodes at zero.
    cudaMemsetAsync(d_out, 0, (size_t)out_size * sizeof(float), 0);

    long long total_items = E * CHUNKS;  // 25.6M threads
    int threads = 256;
    long long blocks = (total_items + threads - 1) / threads;
    mp_scatter_kernel<<<(unsigned)blocks, threads>>>(x, src, dst, out, total_items);
}

// round 4
// speedup vs baseline: 1.0750x; 1.0750x over previous
#include <cuda_runtime.h>
#include <cstdint>

// MessagePassing scatter-add:  out[dst[e], :] += x[src[e], :]
// x: [N, 64] f32, edge_index: [2, E] int32 (harness-narrowed), out: [N, 64] f32.
//
// R3: ILP batching. Each warp = 2 edge-slots x 16 chunk-lanes; each thread
// processes U=4 edges with indices hoisted, gathers issued back-to-back
// (MLP=4), then 4 vector no-return reductions.

static constexpr int D = 64;
static constexpr int CHUNKS = D / 4;   // 16 float4 per row
static constexpr int U = 4;            // edges per thread
static constexpr int EDGES_PER_WARP = 2 * U;

__global__ void __launch_bounds__(256) mp_scatter_kernel(
    const float4* __restrict__ x,
    const int* __restrict__ src,
    const int* __restrict__ dst,
    float* __restrict__ out,
    long long E) {
    const int lane = threadIdx.x & 31;
    const int half = lane >> 4;          // edge slot within warp (0/1)
    const int c = lane & 15;             // float4 chunk within row
    const long long w = ((long long)blockIdx.x * blockDim.x + threadIdx.x) >> 5;
    const long long e_base = w * EDGES_PER_WARP + half;

    // 1) hoist indices (independent loads; uniform across each 16-lane half)
    int s[U], d[U];
    bool ok[U];
#pragma unroll
    for (int i = 0; i < U; i++) {
        long long e = e_base + 2 * i;
        ok[i] = (e < E);
        long long ec = ok[i] ? e : 0;
        s[i] = __ldg(&src[ec]);
        d[i] = __ldg(&dst[ec]);
    }

    // 2) gathers in flight (MLP = U)
    float4 v[U];
#pragma unroll
    for (int i = 0; i < U; i++) {
        v[i] = __ldg(&x[(long long)s[i] * CHUNKS + c]);
    }

    // 3) vector no-return reductions
#pragma unroll
    for (int i = 0; i < U; i++) {
        if (ok[i]) {
            float* p = out + (long long)d[i] * D + c * 4;
            asm volatile("red.global.add.v4.f32 [%0], {%1, %2, %3, %4};"
                         :: "l"(p), "f"(v[i].x), "f"(v[i].y), "f"(v[i].z), "f"(v[i].w)
                         : "memory");
        }
    }
}

extern "C" void kernel_launch(void* const* d_in, const int* in_sizes, int n_in,
                              void* d_out, int out_size) {
    const float4* x = (const float4*)d_in[0];    // [N, 64] f32 as float4[N*16]
    const int* ei = (const int*)d_in[1];         // [2, E] int32
    float* out = (float*)d_out;

    long long E = (long long)in_sizes[1] / 2;
    const int* src = ei;
    const int* dst = ei + E;

    cudaMemsetAsync(d_out, 0, (size_t)out_size * sizeof(float), 0);

    // one warp per EDGES_PER_WARP edges
    long long warps = (E + EDGES_PER_WARP - 1) / EDGES_PER_WARP;
    long long threads_total = warps * 32;
    int threads = 256;
    long long blocks = (threads_total + threads - 1) / threads;
    mp_scatter_kernel<<<(unsigned)blocks, threads>>>(x, src, dst, out, E);
}